// round 1
// baseline (speedup 1.0000x reference)
#include <cuda_runtime.h>

// LIF scan: T=16, N = B*C*H*W = 32*128*32*32 = 4,194,304 sites.
// v[t] = v[t-1]*0.5 + I[t]; spike = (v >= 1.0); v -= spike (thr=1, subtract reset).
// Pure streaming kernel: 256 MiB in, 256 MiB out. One thread per float4 (4 sites),
// fully unrolled t-loop so ptxas can hoist independent loads above the serial
// v-dependence chain (maximize MLP against the 577-cyc DRAM latency).

#ifndef LIF_T
#define LIF_T 16
#endif

__global__ void __launch_bounds__(256) lif_kernel(
    const float4* __restrict__ in,   // [T, N/4] float4
    float4* __restrict__ out,        // [T, N/4] float4
    int n4)                          // N/4
{
    const int i = blockIdx.x * blockDim.x + threadIdx.x;
    if (i >= n4) return;

    const float decay = 0.5f;
    const float thr   = 1.0f;

    float vx = 0.0f, vy = 0.0f, vz = 0.0f, vw = 0.0f;

    #pragma unroll
    for (int t = 0; t < LIF_T; ++t) {
        const float4 x = in[(size_t)t * n4 + i];

        vx = fmaf(vx, decay, x.x);
        vy = fmaf(vy, decay, x.y);
        vz = fmaf(vz, decay, x.z);
        vw = fmaf(vw, decay, x.w);

        const float sx = (vx >= thr) ? 1.0f : 0.0f;
        const float sy = (vy >= thr) ? 1.0f : 0.0f;
        const float sz = (vz >= thr) ? 1.0f : 0.0f;
        const float sw = (vw >= thr) ? 1.0f : 0.0f;

        vx -= sx * thr;
        vy -= sy * thr;
        vz -= sz * thr;
        vw -= sw * thr;

        float4 s;
        s.x = sx; s.y = sy; s.z = sz; s.w = sw;
        out[(size_t)t * n4 + i] = s;
    }
}

extern "C" void kernel_launch(void* const* d_in, const int* in_sizes, int n_in,
                              void* d_out, int out_size)
{
    const float* in = (const float*)d_in[0];
    float* out = (float*)d_out;

    const int total = in_sizes[0];            // T * N = 67,108,864
    const int n = total / LIF_T;              // N = 4,194,304 (sites)
    const int n4 = n / 4;                     // 1,048,576 float4 lanes

    const int block = 256;
    const int grid = (n4 + block - 1) / block;

    lif_kernel<<<grid, block>>>((const float4*)in, (float4*)out, n4);
}

// round 2
// speedup vs baseline: 1.0198x; 1.0198x over previous
#include <cuda_runtime.h>

// LIF scan: T=16, N = 4,194,304 sites. HBM-bound streaming (256 MiB in, 256 MiB out).
// R1: 79.7% DRAM busy @ regs=32 (MLP~2, fine-grained ld/st interleave).
// R2 change: batch the time loop in groups of 8 -> 8 front-batched LDG.128
// (MLP=8), serial v-chain in regs, then 8 batched STG.128. Coarsens the DRAM
// read/write phases (less bus turnaround) and raises per-thread MLP.
// .cs hints: zero reuse, evict-first.

#ifndef LIF_T
#define LIF_T 16
#endif
#define TBATCH 8

__global__ void __launch_bounds__(256) lif_kernel(
    const float4* __restrict__ in,   // [T, N/4] float4
    float4* __restrict__ out,        // [T, N/4] float4
    int n4)                          // N/4
{
    const int i = blockIdx.x * blockDim.x + threadIdx.x;
    if (i >= n4) return;

    const float decay = 0.5f;
    const float thr   = 1.0f;

    float vx = 0.0f, vy = 0.0f, vz = 0.0f, vw = 0.0f;

    const float4* __restrict__ ip = in + i;
    float4* __restrict__ op = out + i;

    #pragma unroll
    for (int tb = 0; tb < LIF_T; tb += TBATCH) {
        // Phase 1: front-batched loads (8 independent LDG.128 in flight)
        float4 x[TBATCH];
        #pragma unroll
        for (int j = 0; j < TBATCH; ++j) {
            x[j] = __ldcs(ip + (size_t)(tb + j) * n4);
        }

        // Phase 2: serial LIF chain entirely in registers
        #pragma unroll
        for (int j = 0; j < TBATCH; ++j) {
            vx = fmaf(vx, decay, x[j].x);
            vy = fmaf(vy, decay, x[j].y);
            vz = fmaf(vz, decay, x[j].z);
            vw = fmaf(vw, decay, x[j].w);

            const float sx = (vx >= thr) ? 1.0f : 0.0f;
            const float sy = (vy >= thr) ? 1.0f : 0.0f;
            const float sz = (vz >= thr) ? 1.0f : 0.0f;
            const float sw = (vw >= thr) ? 1.0f : 0.0f;

            vx -= sx * thr;
            vy -= sy * thr;
            vz -= sz * thr;
            vw -= sw * thr;

            x[j].x = sx; x[j].y = sy; x[j].z = sz; x[j].w = sw;
        }

        // Phase 3: batched stores (8 back-to-back STG.128)
        #pragma unroll
        for (int j = 0; j < TBATCH; ++j) {
            __stcs(op + (size_t)(tb + j) * n4, x[j]);
        }
    }
}

extern "C" void kernel_launch(void* const* d_in, const int* in_sizes, int n_in,
                              void* d_out, int out_size)
{
    const float* in = (const float*)d_in[0];
    float* out = (float*)d_out;

    const int total = in_sizes[0];            // T * N = 67,108,864
    const int n = total / LIF_T;              // N = 4,194,304 (sites)
    const int n4 = n / 4;                     // 1,048,576 float4 lanes

    const int block = 256;
    const int grid = (n4 + block - 1) / block;

    lif_kernel<<<grid, block>>>((const float4*)in, (float4*)out, n4);
}

// round 3
// speedup vs baseline: 1.0214x; 1.0016x over previous
#include <cuda_runtime.h>

// LIF scan: T=16, N = 4,194,304 sites. HBM-bound streaming (256 MiB in, 256 MiB out).
// R1 (plain loop, regs=32, occ 85%):   DRAM 79.7%, 84.0 us
// R2 (TBATCH=8,   regs=40, occ 64%):   DRAM 80.3%, 82.4 us
//   -> request supply is NOT the limiter; suspect DRAM read/write turnaround.
// R3: TBATCH=16 — fully separate phases per warp: 16 back-to-back LDG.128,
// serial v-chain in registers, 16 back-to-back STG.128. Maximal same-direction
// burst length the kernel can offer the memory controller.

#ifndef LIF_T
#define LIF_T 16
#endif

__global__ void __launch_bounds__(256) lif_kernel(
    const float4* __restrict__ in,   // [T, N/4] float4
    float4* __restrict__ out,        // [T, N/4] float4
    int n4)                          // N/4
{
    const int i = blockIdx.x * blockDim.x + threadIdx.x;
    if (i >= n4) return;

    const float decay = 0.5f;
    const float thr   = 1.0f;

    const float4* __restrict__ ip = in + i;
    float4* __restrict__ op = out + i;

    // Phase 1: all 16 loads in flight (streaming, evict-first)
    float4 x[LIF_T];
    #pragma unroll
    for (int t = 0; t < LIF_T; ++t) {
        x[t] = __ldcs(ip + (size_t)t * n4);
    }

    // Phase 2: serial LIF chain entirely in registers
    float vx = 0.0f, vy = 0.0f, vz = 0.0f, vw = 0.0f;
    #pragma unroll
    for (int t = 0; t < LIF_T; ++t) {
        vx = fmaf(vx, decay, x[t].x);
        vy = fmaf(vy, decay, x[t].y);
        vz = fmaf(vz, decay, x[t].z);
        vw = fmaf(vw, decay, x[t].w);

        const float sx = (vx >= thr) ? 1.0f : 0.0f;
        const float sy = (vy >= thr) ? 1.0f : 0.0f;
        const float sz = (vz >= thr) ? 1.0f : 0.0f;
        const float sw = (vw >= thr) ? 1.0f : 0.0f;

        vx -= sx * thr;
        vy -= sy * thr;
        vz -= sz * thr;
        vw -= sw * thr;

        x[t].x = sx; x[t].y = sy; x[t].z = sz; x[t].w = sw;
    }

    // Phase 3: all 16 stores back-to-back (streaming, evict-first)
    #pragma unroll
    for (int t = 0; t < LIF_T; ++t) {
        __stcs(op + (size_t)t * n4, x[t]);
    }
}

extern "C" void kernel_launch(void* const* d_in, const int* in_sizes, int n_in,
                              void* d_out, int out_size)
{
    const float* in = (const float*)d_in[0];
    float* out = (float*)d_out;

    const int total = in_sizes[0];            // T * N = 67,108,864
    const int n = total / LIF_T;              // N = 4,194,304 (sites)
    const int n4 = n / 4;                     // 1,048,576 float4 lanes

    const int block = 256;
    const int grid = (n4 + block - 1) / block;

    lif_kernel<<<grid, block>>>((const float4*)in, (float4*)out, n4);
}